// round 7
// baseline (speedup 1.0000x reference)
#include <cuda_runtime.h>

typedef unsigned long long ull;

#define T_STEPS 1024
#define BATCH   64
#define DIN     256
#define H0      512
#define H1      256
#define NCTA    128
#define NTHR    512

// Per-step input vector v (K=1024), staged in 4 chunks of 256 rows x 64 batch:
//   [0,256)    = x_t        (layer0 only)
//   [256,768)  = h0_{t-1}   (layer0 + layer1)
//   [768,1024) = h1_{t-2}   (layer1 only)
// Thread tile: q = tid&15 (batches 4q..4q+3), cl = (tid>>4)&1, ks = tid>>5 (0..15)
//   L0: cl owns 8 gate-cols, k in [48ks, 48ks+48)
//   L1: cl owns 4 gate-cols, local k1 in [48ks, 48ks+48)  (global k = 256+k1)
// 16 ks-partials reduced in two waves through smem (aliased over vbuf).

__device__ float g_xT[T_STEPS * DIN * BATCH];   // x transposed to [t][k][b]
__device__ float g_h0[2][H0 * BATCH];
__device__ float g_h1[2][H1 * BATCH];
__device__ unsigned g_count = 0;
__device__ volatile unsigned g_phase = 0;

__device__ __forceinline__ ull ffma2(ull a, ull b, ull c) {
    ull d;
    asm("fma.rn.f32x2 %0, %1, %2, %3;" : "=l"(d) : "l"(a), "l"(b), "l"(c));
    return d;
}
__device__ __forceinline__ ull addf2(ull a, ull b) {
    ull d;
    asm("add.rn.f32x2 %0, %1, %2;" : "=l"(d) : "l"(a), "l"(b));
    return d;
}
__device__ __forceinline__ ull dup32(float w) {
    unsigned u = __float_as_uint(w);
    return ((ull)u << 32) | (ull)u;
}
__device__ __forceinline__ float sigmf(float x) {
    return 1.0f / (1.0f + __expf(-x));
}
__device__ __forceinline__ int imax(int a, int b) { return a > b ? a : b; }
__device__ __forceinline__ int imin(int a, int b) { return a < b ? a : b; }

// Sense-reversing grid barrier. Safe: ~219KB smem -> 1 CTA/SM, 128 CTAs <= 148 SMs,
// all co-resident in wave 1. Count self-resets -> consistent across graph replays.
__device__ __forceinline__ void grid_barrier() {
    __syncthreads();
    if (threadIdx.x == 0) {
        __threadfence();
        unsigned ph = g_phase;
        if (atomicAdd(&g_count, 1u) == (unsigned)(gridDim.x - 1)) {
            atomicExch(&g_count, 0u);
            __threadfence();
            g_phase = ph + 1u;
        } else {
            while (g_phase == ph) { __nanosleep(32); }
            __threadfence();
        }
    }
    __syncthreads();
}

__global__ void __launch_bounds__(NTHR, 1)
lstm2_kernel(const float* __restrict__ x,
             const float* __restrict__ Wih0, const float* __restrict__ bih0,
             const float* __restrict__ Whh0, const float* __restrict__ bhh0,
             const float* __restrict__ Wih1, const float* __restrict__ bih1,
             const float* __restrict__ Whh1, const float* __restrict__ bhh1,
             float* __restrict__ out)
{
    extern __shared__ char smraw[];
    ull*   w0d    = reinterpret_cast<ull*>(smraw);            // [768][16] lane-dup
    ull*   w1d    = w0d + 768 * 16;                           // [768][8]
    float* bcol   = reinterpret_cast<float*>(w1d + 768 * 8);  // [24]
    float* gates0 = bcol + 24;                                // [16][64]
    float* gates1 = gates0 + 16 * BATCH;                      // [8][64]
    float* fbase  = gates1 + 8 * BATCH;                       // 16B-aligned union
    float* vbuf   = fbase;                                    // [256][64] contiguous
    ulonglong2* red2 = reinterpret_cast<ulonglong2*>(fbase);  // [24][8][16] partial pairs

    const int tid = threadIdx.x;
    const int cta = blockIdx.x;
    const int q   = tid & 15;            // batch quad: 4q..4q+3
    const int cl  = (tid >> 4) & 1;
    const int ks  = tid >> 5;            // 0..15 == warp id
    const int ks8 = ks & 7;
    const int L0lo = 48 * ks, L0hi = L0lo + 48;
    const int k1lo = 48 * ks, k1hi = k1lo + 48;   // layer1 local k

    // ---- one-time: transpose x (B,T,K) -> g_xT (T,K,B); coalesced writes ----
    {
        const size_t total = (size_t)BATCH * T_STEPS * (DIN / 4);
        for (size_t idx = (size_t)cta * NTHR + tid; idx < total; idx += (size_t)NCTA * NTHR) {
            int b  = (int)(idx & 63);
            size_t r = idx >> 6;
            int kg = (int)(r & 63);
            int t  = (int)(r >> 6);
            float4 v4 = *reinterpret_cast<const float4*>(
                x + ((size_t)b * T_STEPS + t) * DIN + kg * 4);
            float* dst = g_xT + ((size_t)t * DIN + kg * 4) * BATCH + b;
            dst[0 * BATCH] = v4.x;
            dst[1 * BATCH] = v4.y;
            dst[2 * BATCH] = v4.z;
            dst[3 * BATCH] = v4.w;
        }
    }

    // ---- one-time: stage weights into smem (lane-duplicated for f32x2) ----
    // L0 smem col c = cl_*8 + g*2 + up -> unit u = 2*cl_+up, global j = g*512 + cta*4 + u
    for (int idx = tid; idx < 768 * 16; idx += NTHR) {
        int k = idx >> 4, c = idx & 15;
        int cl_ = c >> 3, g = (c >> 1) & 3, up = c & 1;
        int j = g * 512 + cta * 4 + 2 * cl_ + up;
        float w = (k < 256) ? Wih0[(size_t)k * 2048 + j]
                            : Whh0[(size_t)(k - 256) * 2048 + j];
        w0d[idx] = dup32(w);
    }
    // L1 smem col c = cl_*4 + g -> unit u1 = cl_, global j = g*256 + cta*2 + cl_
    for (int idx = tid; idx < 768 * 8; idx += NTHR) {
        int k = idx >> 3, c = idx & 7;
        int cl_ = c >> 2, g = c & 3;
        int j = g * 256 + cta * 2 + cl_;
        float w = (k < 512) ? Wih1[(size_t)k * 1024 + j]
                            : Whh1[(size_t)(k - 512) * 1024 + j];
        w1d[idx] = dup32(w);
    }
    if (tid < 16) {
        int cl_ = tid >> 3, g = (tid >> 1) & 3, up = tid & 1;
        int j = g * 512 + cta * 4 + 2 * cl_ + up;
        bcol[tid] = bih0[j] + bhh0[j];
    } else if (tid < 24) {
        int c = tid - 16;
        int cl_ = c >> 2, g = c & 3;
        int j = g * 256 + cta * 2 + cl_;
        bcol[tid] = bih1[j] + bhh1[j];
    }

    float cst = 0.0f;   // c0 for tid<256; c1 for tid in [256,384)

    __syncthreads();
    grid_barrier();     // g_xT complete

    // ---- main recurrence: iteration t = layer0 step t + layer1 step t-1 ----
    for (int t = 0; t <= T_STEPS; t++) {
        ull a0lo[8], a0hi[8], a1lo[4], a1hi[4];
#pragma unroll
        for (int j = 0; j < 8; j++) { a0lo[j] = 0ull; a0hi[j] = 0ull; }
#pragma unroll
        for (int j = 0; j < 4; j++) { a1lo[j] = 0ull; a1hi[j] = 0ull; }

        const bool hasL0 = (t < T_STEPS);
        const bool hasL1 = (t >= 1);

#pragma unroll 1
        for (int ci = 0; ci < 4; ci++) {
            __syncthreads();                 // union area free
            // ---- stage 256x64 chunk into vbuf, contiguous [k][b] ----
            float4* v4 = reinterpret_cast<float4*>(vbuf);
            if (ci == 0) {
                if (hasL0) {
                    const float4* src = reinterpret_cast<const float4*>(
                        g_xT + (size_t)t * DIN * BATCH);
#pragma unroll
                    for (int i = 0; i < 8; i++) v4[tid + i * NTHR] = src[tid + i * NTHR];
                }
            } else if (ci < 3) {
                if (t >= 1) {
                    const float4* src = reinterpret_cast<const float4*>(
                        g_h0[(t - 1) & 1] + (ci - 1) * 256 * BATCH);
#pragma unroll
                    for (int i = 0; i < 8; i++) v4[tid + i * NTHR] = src[tid + i * NTHR];
                } else {
#pragma unroll
                    for (int i = 0; i < 8; i++)
                        v4[tid + i * NTHR] = make_float4(0.f, 0.f, 0.f, 0.f);
                }
            } else {
                if (t >= 2) {
                    const float4* src = reinterpret_cast<const float4*>(g_h1[t & 1]);
#pragma unroll
                    for (int i = 0; i < 8; i++) v4[tid + i * NTHR] = src[tid + i * NTHR];
                } else {
#pragma unroll
                    for (int i = 0; i < 8; i++)
                        v4[tid + i * NTHR] = make_float4(0.f, 0.f, 0.f, 0.f);
                }
            }
            __syncthreads();

            const int cbase = ci << 8;
            // ---- L0 GEMM slice: 8 cols x 4 batches ----
            if (hasL0) {
                int lo = imax(L0lo, cbase), hi = imin(L0hi, cbase + 256);
                if (lo < hi) {
                    const ulonglong2* wp = reinterpret_cast<const ulonglong2*>(
                        w0d + lo * 16 + cl * 8);
                    const ulonglong2* vp = reinterpret_cast<const ulonglong2*>(
                        vbuf + (lo - cbase) * 64 + 4 * q);
#pragma unroll 2
                    for (int k = lo; k < hi; k++) {
                        ulonglong2 vv = *vp; vp += 16;           // 64 floats = 16 u2 per row
                        ulonglong2 wA = wp[0], wB = wp[1], wC = wp[2], wD = wp[3];
                        wp += 8;                                  // 16 ull per k-row
                        a0lo[0] = ffma2(wA.x, vv.x, a0lo[0]); a0hi[0] = ffma2(wA.x, vv.y, a0hi[0]);
                        a0lo[1] = ffma2(wA.y, vv.x, a0lo[1]); a0hi[1] = ffma2(wA.y, vv.y, a0hi[1]);
                        a0lo[2] = ffma2(wB.x, vv.x, a0lo[2]); a0hi[2] = ffma2(wB.x, vv.y, a0hi[2]);
                        a0lo[3] = ffma2(wB.y, vv.x, a0lo[3]); a0hi[3] = ffma2(wB.y, vv.y, a0hi[3]);
                        a0lo[4] = ffma2(wC.x, vv.x, a0lo[4]); a0hi[4] = ffma2(wC.x, vv.y, a0hi[4]);
                        a0lo[5] = ffma2(wC.y, vv.x, a0lo[5]); a0hi[5] = ffma2(wC.y, vv.y, a0hi[5]);
                        a0lo[6] = ffma2(wD.x, vv.x, a0lo[6]); a0hi[6] = ffma2(wD.x, vv.y, a0hi[6]);
                        a0lo[7] = ffma2(wD.y, vv.x, a0lo[7]); a0hi[7] = ffma2(wD.y, vv.y, a0hi[7]);
                    }
                }
            }
            // ---- L1 GEMM slice: 4 cols x 4 batches ----
            if (hasL1) {
                int lo = imax(k1lo, cbase - 256), hi = imin(k1hi, cbase);
                if (lo < hi) {
                    const ulonglong2* wp = reinterpret_cast<const ulonglong2*>(
                        w1d + lo * 8 + cl * 4);
                    const ulonglong2* vp = reinterpret_cast<const ulonglong2*>(
                        vbuf + (lo + 256 - cbase) * 64 + 4 * q);
#pragma unroll 4
                    for (int k = lo; k < hi; k++) {
                        ulonglong2 vv = *vp; vp += 16;
                        ulonglong2 wA = wp[0], wB = wp[1];
                        wp += 4;                                  // 8 ull per k1-row
                        a1lo[0] = ffma2(wA.x, vv.x, a1lo[0]); a1hi[0] = ffma2(wA.x, vv.y, a1hi[0]);
                        a1lo[1] = ffma2(wA.y, vv.x, a1lo[1]); a1hi[1] = ffma2(wA.y, vv.y, a1hi[1]);
                        a1lo[2] = ffma2(wB.x, vv.x, a1lo[2]); a1hi[2] = ffma2(wB.x, vv.y, a1hi[2]);
                        a1lo[3] = ffma2(wB.y, vv.x, a1lo[3]); a1hi[3] = ffma2(wB.y, vv.y, a1hi[3]);
                    }
                }
            }
        }

        __syncthreads();     // gemm reads done -> red2 (aliased) safe
        // ---- two-wave ks reduction: red2[c][ks8][q] ----
        if (ks < 8) {
#pragma unroll
            for (int j = 0; j < 8; j++)
                red2[(((cl << 3) + j) * 8 + ks8) * 16 + q] = make_ulonglong2(a0lo[j], a0hi[j]);
#pragma unroll
            for (int j = 0; j < 4; j++)
                red2[((16 + (cl << 2) + j) * 8 + ks8) * 16 + q] = make_ulonglong2(a1lo[j], a1hi[j]);
        }
        __syncthreads();
        if (ks >= 8) {
#pragma unroll
            for (int j = 0; j < 8; j++) {
                int idx = (((cl << 3) + j) * 8 + ks8) * 16 + q;
                ulonglong2 r = red2[idx];
                r.x = addf2(r.x, a0lo[j]); r.y = addf2(r.y, a0hi[j]);
                red2[idx] = r;
            }
#pragma unroll
            for (int j = 0; j < 4; j++) {
                int idx = ((16 + (cl << 2) + j) * 8 + ks8) * 16 + q;
                ulonglong2 r = red2[idx];
                r.x = addf2(r.x, a1lo[j]); r.y = addf2(r.y, a1hi[j]);
                red2[idx] = r;
            }
        }
        __syncthreads();

        // ---- final reduce: 24 cols x 16 quads, sum 8 partials + bias -> gates ----
        if (tid < 384) {
            int c = tid >> 4, qq = tid & 15;
            const ulonglong2* r = red2 + (c * 8) * 16 + qq;
            ull bb = dup32(bcol[c]);
            ull slo = bb, shi = bb;
#pragma unroll
            for (int s = 0; s < 8; s++) {
                ulonglong2 v = r[s * 16];
                slo = addf2(slo, v.x);
                shi = addf2(shi, v.y);
            }
            ulonglong2 res = make_ulonglong2(slo, shi);
            if (c < 16) {
                int cl_ = c >> 3, g = (c >> 1) & 3, up = c & 1;
                int u = 2 * cl_ + up;
                *reinterpret_cast<ulonglong2*>(&gates0[(g * 4 + u) * BATCH + 4 * qq]) = res;
            } else {
                int cc1 = c - 16, cl_ = cc1 >> 2, g = cc1 & 3;
                *reinterpret_cast<ulonglong2*>(&gates1[(g * 2 + cl_) * BATCH + 4 * qq]) = res;
            }
        }
        __syncthreads();

        // ---- activations (disjoint warps) ----
        if (hasL0 && tid < 256) {
            int u = tid >> 6, b = tid & 63;
            float gi = gates0[(u)      * BATCH + b];
            float gf = gates0[(4 + u)  * BATCH + b];
            float gg = gates0[(8 + u)  * BATCH + b];
            float go = gates0[(12 + u) * BATCH + b];
            cst = sigmf(gf) * cst + sigmf(gi) * tanhf(gg);
            g_h0[t & 1][(cta * 4 + u) * BATCH + b] = sigmf(go) * tanhf(cst);
        }
        if (hasL1 && tid >= 256 && tid < 384) {
            int u1 = (tid >> 6) & 1, b = tid & 63;
            float gi = gates1[(u1)     * BATCH + b];
            float gf = gates1[(2 + u1) * BATCH + b];
            float gg = gates1[(4 + u1) * BATCH + b];
            float go = gates1[(6 + u1) * BATCH + b];
            cst = sigmf(gf) * cst + sigmf(gi) * tanhf(gg);
            float h = sigmf(go) * tanhf(cst);
            int s = t - 1;
            g_h1[s & 1][(cta * 2 + u1) * BATCH + b] = h;
            out[((size_t)b * T_STEPS + s) * H1 + cta * 2 + u1] = h;
        }

        if (t < T_STEPS) grid_barrier();
    }
}

// smem: weights 147456 + bcol 96 + gates 6144 + union max(vbuf 65536, red 49152)
#define SMEM_BYTES (147456 + 96 + 6144 + 65536)

extern "C" void kernel_launch(void* const* d_in, const int* in_sizes, int n_in,
                              void* d_out, int out_size) {
    (void)in_sizes; (void)n_in; (void)out_size;
    cudaFuncSetAttribute(lstm2_kernel,
                         cudaFuncAttributeMaxDynamicSharedMemorySize, SMEM_BYTES);
    lstm2_kernel<<<NCTA, NTHR, SMEM_BYTES>>>(
        (const float*)d_in[0],
        (const float*)d_in[1], (const float*)d_in[2],
        (const float*)d_in[3], (const float*)d_in[4],
        (const float*)d_in[5], (const float*)d_in[6],
        (const float*)d_in[7], (const float*)d_in[8],
        (float*)d_out);
}